// round 6
// baseline (speedup 1.0000x reference)
#include <cuda_runtime.h>
#include <math.h>
#include <stdint.h>

// Problem constants
#define BB   4
#define SS   2048
#define HH   2048
#define NHH  16
#define NKV  4
#define HD   128
#define MTOK (BB*SS)          // 8192 tokens
#define NQKV 3072             // (16 + 2*4) * 128
#define KOFF 2048
#define VOFF 2560

// Scratch (allocation rules forbid cudaMalloc)
__device__ float g_qkv[(size_t)MTOK * NQKV];   // ~100.7 MB
__device__ float g_attn[(size_t)MTOK * HH];    // 64 MB

// ---------------------------------------------------------------------------
// Helpers
// ---------------------------------------------------------------------------
__device__ __forceinline__ uint32_t f2tf32(float x) {
    uint32_t y;
    asm("cvt.rna.tf32.f32 %0, %1;" : "=r"(y) : "f"(x));
    return y;
}
__device__ __forceinline__ uint32_t rtf32(uint32_t raw) {   // raw fp32 bits -> tf32 (rna)
    return f2tf32(__uint_as_float(raw));
}
__device__ __forceinline__ void split_u(uint32_t raw, uint32_t& hi, uint32_t& lo) {
    const float x = __uint_as_float(raw);
    hi = f2tf32(x);
    lo = f2tf32(x - __uint_as_float(hi));
}
__device__ __forceinline__ uint4 tf32x4(float4 v) {
    return make_uint4(f2tf32(v.x), f2tf32(v.y), f2tf32(v.z), f2tf32(v.w));
}
__device__ __forceinline__ uint32_t smem_u32(const void* p) {
    return (uint32_t)__cvta_generic_to_shared(p);
}
__device__ __forceinline__ void ldmatrix_x4(uint32_t* d, uint32_t addr) {
    asm volatile("ldmatrix.sync.aligned.m8n8.x4.shared.b16 {%0,%1,%2,%3}, [%4];"
                 : "=r"(d[0]), "=r"(d[1]), "=r"(d[2]), "=r"(d[3])
                 : "r"(addr));
}
__device__ __forceinline__ void mma_tf32(float* c, const uint32_t* a, const uint32_t* b) {
    asm volatile(
        "mma.sync.aligned.m16n8k8.row.col.f32.tf32.tf32.f32 "
        "{%0,%1,%2,%3}, {%4,%5,%6,%7}, {%8,%9}, {%0,%1,%2,%3};"
        : "+f"(c[0]), "+f"(c[1]), "+f"(c[2]), "+f"(c[3])
        : "r"(a[0]), "r"(a[1]), "r"(a[2]), "r"(a[3]), "r"(b[0]), "r"(b[1]));
}
#define CP16(dst, src) \
    asm volatile("cp.async.cg.shared.global [%0], [%1], 16;" :: "r"(dst), "l"(src) : "memory")
#define CP4(dst, src) \
    asm volatile("cp.async.ca.shared.global [%0], [%1], 4;" :: "r"(dst), "l"(src) : "memory")
#define CP_COMMIT()  asm volatile("cp.async.commit_group;" ::: "memory")
#define CP_WAIT(n)   asm volatile("cp.async.wait_group " #n ";" ::: "memory")

// ---------------------------------------------------------------------------
// 3xTF32 GEMM with cp.async 4-stage pipeline, raw-fp32 smem, register split.
// C = A*B + bias. CTA 128x128x32, 256 thr = 8 warps (4m x 2n), warp 32x64.
// Stage layout (u32): A[128*32] swizzled, then B^T[128*32] swizzled.
// ---------------------------------------------------------------------------
#define GSTAGE_U32 (2 * 128 * 32)
#define GSTAGES 4
#define GEMM_SMEM_BYTES (GSTAGES * GSTAGE_U32 * 4)    // 128 KB

__device__ __forceinline__ void gemm_issue_stage(
    const float* A, const float* Bw, int K, int N,
    int m0, int n0, int k0, uint32_t sBase, int tid)
{
#pragma unroll
    for (int it = 0; it < 4; ++it) {       // A: 16B chunks
        const int idx = tid + 256 * it;
        const int am = idx >> 3, ak4 = idx & 7;
        const uint32_t dst = sBase + 4u * (am * 32 + 4 * (ak4 ^ (am & 7)));
        CP16(dst, A + (size_t)(m0 + am) * K + k0 + 4 * ak4);
    }
#pragma unroll
    for (int it = 0; it < 16; ++it) {      // B: 4B scattered transpose
        const int idx = tid + 256 * it;
        const int bn = idx & 127, bk = idx >> 7;
        const uint32_t dst = sBase + 4u * (128 * 32 + bn * 32 +
                                           4 * ((bk >> 2) ^ (bn & 7)) + (bk & 3));
        CP4(dst, Bw + (size_t)(k0 + bk) * N + n0 + bn);
    }
}

__global__ __launch_bounds__(256)
void gemm_tf32x3_kernel(const float* __restrict__ A,
                        const float* __restrict__ Bw,
                        const float* __restrict__ bias,
                        float* __restrict__ C,
                        int M, int N, int K)
{
    extern __shared__ uint32_t gsm[];

    const int tid  = threadIdx.x;
    const int lane = tid & 31;
    const int warp = tid >> 5;
    const int wm   = (warp >> 1) * 32;
    const int wn   = (warp & 1) * 64;
    const int m0   = blockIdx.y * 128;
    const int n0   = blockIdx.x * 128;

    const int q = lane >> 3;
    const int r = lane & 7;
    const int rowA0 = wm + 8 * (q & 1) + r;
    const int rowB0 = wn + 8 * (q >> 1) + r;

    const uint32_t smBase = smem_u32(gsm);

    float acc[2][8][4];
#pragma unroll
    for (int i = 0; i < 2; i++)
#pragma unroll
        for (int j = 0; j < 8; j++)
#pragma unroll
            for (int v = 0; v < 4; v++) acc[i][j][v] = 0.0f;

    const int nk = K >> 5;

    // prologue: stages 0..2
#pragma unroll
    for (int t = 0; t < 3; ++t) {
        gemm_issue_stage(A, Bw, K, N, m0, n0, t << 5,
                         smBase + (uint32_t)(t * GSTAGE_U32 * 4), tid);
        CP_COMMIT();
    }

    for (int t = 0; t < nk; ++t) {
        CP_WAIT(2);
        __syncthreads();

        if (t + 3 < nk)
            gemm_issue_stage(A, Bw, K, N, m0, n0, (t + 3) << 5,
                             smBase + (uint32_t)(((t + 3) & 3) * GSTAGE_U32 * 4), tid);
        CP_COMMIT();

        const uint32_t sA = smBase + (uint32_t)((t & 3) * GSTAGE_U32 * 4);
        const uint32_t sB = sA + 128 * 32 * 4;

#pragma unroll
        for (int s = 0; s < 4; ++s) {
            const int ka = (2 * s + (q >> 1)) ^ r;
            uint32_t ah[2][4], al[2][4];
#pragma unroll
            for (int mi = 0; mi < 2; ++mi) {
                uint32_t ar[4];
                ldmatrix_x4(ar, sA + (uint32_t)(((rowA0 + 16 * mi) * 32 + 4 * ka) << 2));
#pragma unroll
                for (int e = 0; e < 4; e++) split_u(ar[e], ah[mi][e], al[mi][e]);
            }
            const int kb = (2 * s + (q & 1)) ^ r;
#pragma unroll
            for (int jp = 0; jp < 4; ++jp) {
                uint32_t tr[4];
                ldmatrix_x4(tr, sB + (uint32_t)(((rowB0 + 16 * jp) * 32 + 4 * kb) << 2));
                uint32_t th[4], tl[4];
#pragma unroll
                for (int e = 0; e < 4; e++) split_u(tr[e], th[e], tl[e]);
                uint32_t bh0[2] = { th[0], th[1] }, bh1[2] = { th[2], th[3] };
                uint32_t bl0[2] = { tl[0], tl[1] }, bl1[2] = { tl[2], tl[3] };
#pragma unroll
                for (int mi = 0; mi < 2; ++mi) {
                    mma_tf32(acc[mi][2 * jp], ah[mi], bh0);
                    mma_tf32(acc[mi][2 * jp], ah[mi], bl0);
                    mma_tf32(acc[mi][2 * jp], al[mi], bh0);
                    mma_tf32(acc[mi][2 * jp + 1], ah[mi], bh1);
                    mma_tf32(acc[mi][2 * jp + 1], ah[mi], bl1);
                    mma_tf32(acc[mi][2 * jp + 1], al[mi], bh1);
                }
            }
        }
    }

    // epilogue: acc + bias -> C
    const int gg  = lane >> 2;
    const int tig = lane & 3;
#pragma unroll
    for (int mi = 0; mi < 2; ++mi) {
#pragma unroll
        for (int nj = 0; nj < 8; ++nj) {
            const int row = m0 + wm + 16 * mi + gg;
            const int col = n0 + wn + 8 * nj + 2 * tig;
            const float b0v = __ldg(bias + col);
            const float b1v = __ldg(bias + col + 1);
            float2 v0 = make_float2(acc[mi][nj][0] + b0v, acc[mi][nj][1] + b1v);
            float2 v1 = make_float2(acc[mi][nj][2] + b0v, acc[mi][nj][3] + b1v);
            *(float2*)(C + (size_t)row * N + col)       = v0;
            *(float2*)(C + (size_t)(row + 8) * N + col) = v1;
        }
    }
}

// ---------------------------------------------------------------------------
// RoPE (full rotation, ROT == HD == 128), in-place on Q and K heads.
// ---------------------------------------------------------------------------
__global__ __launch_bounds__(256)
void rope_kernel(float* __restrict__ qkv,
                 const float* __restrict__ cosp,
                 const float* __restrict__ sinp)
{
    const int total = MTOK * (NHH + NKV) * 64;
    int idx = blockIdx.x * blockDim.x + threadIdx.x;
    if (idx >= total) return;
    const int t    = idx / ((NHH + NKV) * 64);
    const int rem  = idx - t * ((NHH + NKV) * 64);
    const int head = rem >> 6;
    const int j    = rem & 63;
    const int base = (head < NHH) ? head * HD : KOFF + (head - NHH) * HD;

    float* p = qkv + (size_t)t * NQKV + base;
    const float x1 = p[j];
    const float x2 = p[j + 64];
    const float* cp = cosp + (size_t)t * 128;
    const float* sp = sinp + (size_t)t * 128;
    p[j]      = x1 * cp[j]      - x2 * sp[j];
    p[j + 64] = x2 * cp[j + 64] + x1 * sp[j + 64];
}

// ---------------------------------------------------------------------------
// Tensor-core flash attention with cp.async 2-stage K/V pipeline.
// CTA: 128 q-rows x one head, 8 warps x 16 q-rows, kv tiles of 64.
// Smem (u32): stage s: K[64*128] swizzled @ s*16896, V[64*136] @ s*16896+8192;
// Ps[128*64] swizzled @ 33792.  Q staged in [0, 16384) before pipeline starts.
// K/V stored as RAW fp32; tf32 rna-rounding applied in registers (numerics
// identical to the R5 kernel).
// ---------------------------------------------------------------------------
#define AT_STAGE_U32 16896                 // 64*128 + 64*136
#define AT_P_U32     (2 * AT_STAGE_U32)    // 33792
#define AT_BYTES     ((AT_P_U32 + 128 * 64) * 4)   // 167936

__device__ __forceinline__ void attn_issue_kv(
    const float* qkv, int tk0, int g, uint32_t sK, uint32_t sV, int tid)
{
#pragma unroll
    for (int i = 0; i < 8; i++) {
        const int idx = tid + 256 * i;
        const int row = idx >> 5, c4 = idx & 31;
        const float* srck = qkv + (size_t)(tk0 + row) * NQKV + KOFF + g * HD + 4 * c4;
        const float* srcv = qkv + (size_t)(tk0 + row) * NQKV + VOFF + g * HD + 4 * c4;
        CP16(sK + 4u * (row * 128 + 4 * (c4 ^ (row & 7))), srck);
        CP16(sV + 4u * (row * 136 + 4 * c4), srcv);
    }
}

__global__ __launch_bounds__(256)
void attn_tc_kernel(const float* __restrict__ qkv, float* __restrict__ attn_out)
{
    extern __shared__ uint32_t sm[];
    uint32_t* Qst = sm;                    // prologue only (inside stage 0)
    uint32_t* Ps  = sm + AT_P_U32;

    const int tid  = threadIdx.x;
    const int lane = tid & 31;
    const int warp = tid >> 5;
    const int h    = blockIdx.y;
    const int b    = blockIdx.z;
    const int g    = h >> 2;
    const int tq0  = b * SS + blockIdx.x * 128;
    const int wq0  = warp * 16;
    const int qq   = lane >> 3;
    const int r    = lane & 7;
    const int gg   = lane >> 2;
    const int t4   = lane & 3;
    const float scale = 0.08838834764831845f;

    const uint32_t smBase = smem_u32(sm);
    const uint32_t sP     = smBase + AT_P_U32 * 4;

    // ---- stage Q (scaled, tf32-rna, swizzled) ----
#pragma unroll
    for (int i = 0; i < 16; i++) {
        const int idx = tid + 256 * i;
        const int row = idx >> 5, c4 = idx & 31;
        float4 v = *(const float4*)(qkv + (size_t)(tq0 + row) * NQKV + h * HD + 4 * c4);
        v.x *= scale; v.y *= scale; v.z *= scale; v.w *= scale;
        *(uint4*)&Qst[row * 128 + 4 * (c4 ^ (row & 7))] = tf32x4(v);
    }
    __syncthreads();

    uint32_t qf[16][4];
    {
        const int rowA = wq0 + 8 * (qq & 1) + r;
#pragma unroll
        for (int s = 0; s < 16; s++) {
            const int k4 = (2 * s + (qq >> 1)) ^ r;
            ldmatrix_x4(qf[s], smBase + (uint32_t)((rowA * 128 + 4 * k4) << 2));
        }
    }
    __syncthreads();   // Q region free; start the K/V pipeline

    // prefetch tiles 0 and 1
#pragma unroll
    for (int t = 0; t < 2; ++t) {
        const uint32_t sS = smBase + (uint32_t)(t * AT_STAGE_U32 * 4);
        attn_issue_kv(qkv, b * SS + t * 64, g, sS, sS + 8192 * 4, tid);
        CP_COMMIT();
    }

    float O[16][4];
#pragma unroll
    for (int i = 0; i < 16; i++)
#pragma unroll
        for (int j = 0; j < 4; j++) O[i][j] = 0.0f;
    float m0 = -INFINITY, m1 = -INFINITY, l0 = 0.0f, l1 = 0.0f;

    const int rowB = 8 * (qq >> 1) + r;
    const int rowP = wq0 + 8 * (qq & 1) + r;

    for (int kt = 0; kt < SS / 64; ++kt) {
        CP_WAIT(1);
        __syncthreads();

        const uint32_t sS = smBase + (uint32_t)((kt & 1) * AT_STAGE_U32 * 4);
        const uint32_t sK = sS;
        const uint32_t* Vs = sm + (kt & 1) * AT_STAGE_U32 + 8192;

        // ---- S = Q * K^T ----
        float sacc[8][4];
#pragma unroll
        for (int nj = 0; nj < 8; nj++)
#pragma unroll
            for (int v = 0; v < 4; v++) sacc[nj][v] = 0.0f;

#pragma unroll
        for (int s = 0; s < 16; s++) {
            uint32_t bf[8][2];
            const int k4 = (2 * s + (qq & 1)) ^ r;
#pragma unroll
            for (int jp = 0; jp < 4; jp++) {
                uint32_t tmp[4];
                ldmatrix_x4(tmp, sK + (uint32_t)(((rowB + 16 * jp) * 128 + 4 * k4) << 2));
                bf[2 * jp][0]     = rtf32(tmp[0]);
                bf[2 * jp][1]     = rtf32(tmp[1]);
                bf[2 * jp + 1][0] = rtf32(tmp[2]);
                bf[2 * jp + 1][1] = rtf32(tmp[3]);
            }
#pragma unroll
            for (int nj = 0; nj < 8; nj++)
                mma_tf32(sacc[nj], qf[s], bf[nj]);
        }

        // ---- online softmax ----
        float rm0 = -INFINITY, rm1 = -INFINITY;
#pragma unroll
        for (int nj = 0; nj < 8; nj++) {
            rm0 = fmaxf(rm0, fmaxf(sacc[nj][0], sacc[nj][1]));
            rm1 = fmaxf(rm1, fmaxf(sacc[nj][2], sacc[nj][3]));
        }
        rm0 = fmaxf(rm0, __shfl_xor_sync(0xffffffffu, rm0, 1));
        rm0 = fmaxf(rm0, __shfl_xor_sync(0xffffffffu, rm0, 2));
        rm1 = fmaxf(rm1, __shfl_xor_sync(0xffffffffu, rm1, 1));
        rm1 = fmaxf(rm1, __shfl_xor_sync(0xffffffffu, rm1, 2));

        const float mn0 = fmaxf(m0, rm0), mn1 = fmaxf(m1, rm1);
        const float a0 = __expf(m0 - mn0), a1 = __expf(m1 - mn1);
        float rs0 = 0.0f, rs1 = 0.0f;

        const int prow0 = wq0 + gg;
#pragma unroll
        for (int nj = 0; nj < 8; nj++) {
            const float p0 = __expf(sacc[nj][0] - mn0);
            const float p1 = __expf(sacc[nj][1] - mn0);
            const float p2 = __expf(sacc[nj][2] - mn1);
            const float p3 = __expf(sacc[nj][3] - mn1);
            rs0 += p0 + p1; rs1 += p2 + p3;
            const int c4s = (2 * nj + (t4 >> 1)) ^ gg;
            const int sub = 2 * (t4 & 1);
            *(uint2*)&Ps[prow0 * 64 + 4 * c4s + sub]       = make_uint2(f2tf32(p0), f2tf32(p1));
            *(uint2*)&Ps[(prow0 + 8) * 64 + 4 * c4s + sub] = make_uint2(f2tf32(p2), f2tf32(p3));
        }
        rs0 += __shfl_xor_sync(0xffffffffu, rs0, 1);
        rs0 += __shfl_xor_sync(0xffffffffu, rs0, 2);
        rs1 += __shfl_xor_sync(0xffffffffu, rs1, 1);
        rs1 += __shfl_xor_sync(0xffffffffu, rs1, 2);
        l0 = l0 * a0 + rs0; m0 = mn0;
        l1 = l1 * a1 + rs1; m1 = mn1;
#pragma unroll
        for (int nt = 0; nt < 16; nt++) {
            O[nt][0] *= a0; O[nt][1] *= a0;
            O[nt][2] *= a1; O[nt][3] *= a1;
        }
        __syncwarp();

        // ---- O += P * V ----
#pragma unroll
        for (int s2 = 0; s2 < 8; s2++) {
            uint32_t pf[4];
            const int k4 = (2 * s2 + (qq >> 1)) ^ r;
            ldmatrix_x4(pf, sP + (uint32_t)((rowP * 64 + 4 * k4) << 2));
            const uint32_t* v0 = &Vs[(8 * s2 + t4) * 136 + gg];
            const uint32_t* v1 = &Vs[(8 * s2 + t4 + 4) * 136 + gg];
#pragma unroll
            for (int nd = 0; nd < 16; nd++) {
                uint32_t bb[2] = { rtf32(v0[8 * nd]), rtf32(v1[8 * nd]) };
                mma_tf32(O[nd], pf, bb);
            }
        }
        __syncthreads();

        // issue tile kt+2 into the stage we just finished reading
        if (kt + 2 < SS / 64) {
            const uint32_t sN = smBase + (uint32_t)((kt & 1) * AT_STAGE_U32 * 4);
            attn_issue_kv(qkv, b * SS + (kt + 2) * 64, g, sN, sN + 8192 * 4, tid);
        }
        CP_COMMIT();
    }

    // ---- normalize + write ----
    const float inv0 = 1.0f / l0, inv1 = 1.0f / l1;
    const int row0 = tq0 + wq0 + gg;
    float* d0 = attn_out + (size_t)row0 * HH + h * HD;
    float* d1 = attn_out + (size_t)(row0 + 8) * HH + h * HD;
#pragma unroll
    for (int nd = 0; nd < 16; nd++) {
        const int col = 8 * nd + 2 * t4;
        *(float2*)(d0 + col) = make_float2(O[nd][0] * inv0, O[nd][1] * inv0);
        *(float2*)(d1 + col) = make_float2(O[nd][2] * inv1, O[nd][3] * inv1);
    }
}

// ---------------------------------------------------------------------------
// Launch
// ---------------------------------------------------------------------------
extern "C" void kernel_launch(void* const* d_in, const int* in_sizes, int n_in,
                              void* d_out, int out_size)
{
    (void)in_sizes; (void)n_in; (void)out_size;
    const float* hs    = (const float*)d_in[0];
    const float* cosp  = (const float*)d_in[1];
    const float* sinp  = (const float*)d_in[2];
    const float* w_qkv = (const float*)d_in[3];
    const float* b_qkv = (const float*)d_in[4];
    const float* w_o   = (const float*)d_in[5];
    const float* b_o   = (const float*)d_in[6];
    float* out = (float*)d_out;

    float *qkv, *attn;
    cudaGetSymbolAddress((void**)&qkv, g_qkv);
    cudaGetSymbolAddress((void**)&attn, g_attn);

    cudaFuncSetAttribute((const void*)gemm_tf32x3_kernel,
                         cudaFuncAttributeMaxDynamicSharedMemorySize,
                         GEMM_SMEM_BYTES);
    cudaFuncSetAttribute((const void*)attn_tc_kernel,
                         cudaFuncAttributeMaxDynamicSharedMemorySize,
                         AT_BYTES);

    // 1) QKV projection + bias (3xTF32, cp.async pipelined)
    gemm_tf32x3_kernel<<<dim3(NQKV / 128, MTOK / 128), 256, GEMM_SMEM_BYTES>>>(
        hs, w_qkv, b_qkv, qkv, MTOK, NQKV, HH);

    // 2) RoPE on q and k heads (in-place)
    {
        const int total = MTOK * (NHH + NKV) * 64;
        rope_kernel<<<(total + 255) / 256, 256>>>(qkv, cosp, sinp);
    }

    // 3) Tensor-core flash attention (tf32, cp.async pipelined)
    attn_tc_kernel<<<dim3(SS / 128, NHH, BB), 256, AT_BYTES>>>(qkv, attn);

    // 4) Output projection + bias -> d_out (3xTF32)
    gemm_tf32x3_kernel<<<dim3(HH / 128, MTOK / 128), 256, GEMM_SMEM_BYTES>>>(
        attn, w_o, b_o, out, MTOK, HH, HH);
}

// round 10
// speedup vs baseline: 1.1974x; 1.1974x over previous
#include <cuda_runtime.h>
#include <math.h>
#include <stdint.h>

// Problem constants
#define BB   4
#define SS   2048
#define HH   2048
#define NHH  16
#define NKV  4
#define HD   128
#define MTOK (BB*SS)          // 8192 tokens
#define NQKV 3072             // (16 + 2*4) * 128
#define KOFF 2048
#define VOFF 2560

// Scratch (allocation rules forbid cudaMalloc)
__device__ float g_qkv[(size_t)MTOK * NQKV];   // ~100.7 MB
__device__ float g_attn[(size_t)MTOK * HH];    // 64 MB
// Pre-split tf32 hi/lo operands, stored tiled+swizzled in the GEMM smem layout
__device__ float g_Ah[(size_t)MTOK * HH];      // 64 MB
__device__ float g_Al[(size_t)MTOK * HH];      // 64 MB
__device__ float g_Bh[(size_t)HH * NQKV];      // 24 MB
__device__ float g_Bl[(size_t)HH * NQKV];      // 24 MB

// ---------------------------------------------------------------------------
// Helpers
// ---------------------------------------------------------------------------
__device__ __forceinline__ uint32_t f2tf32(float x) {
    uint32_t y;
    asm("cvt.rna.tf32.f32 %0, %1;" : "=r"(y) : "f"(x));
    return y;
}
__device__ __forceinline__ void split_f(float x, uint32_t& hi, uint32_t& lo) {
    hi = f2tf32(x);
    lo = f2tf32(x - __uint_as_float(hi));
}
__device__ __forceinline__ uint4 tf32x4(float4 v) {
    return make_uint4(f2tf32(v.x), f2tf32(v.y), f2tf32(v.z), f2tf32(v.w));
}
__device__ __forceinline__ uint32_t smem_u32(const void* p) {
    return (uint32_t)__cvta_generic_to_shared(p);
}
__device__ __forceinline__ void ldmatrix_x4(uint32_t* d, uint32_t addr) {
    asm volatile("ldmatrix.sync.aligned.m8n8.x4.shared.b16 {%0,%1,%2,%3}, [%4];"
                 : "=r"(d[0]), "=r"(d[1]), "=r"(d[2]), "=r"(d[3])
                 : "r"(addr));
}
__device__ __forceinline__ void mma_tf32(float* c, const uint32_t* a, const uint32_t* b) {
    asm volatile(
        "mma.sync.aligned.m16n8k8.row.col.f32.tf32.tf32.f32 "
        "{%0,%1,%2,%3}, {%4,%5,%6,%7}, {%8,%9}, {%0,%1,%2,%3};"
        : "+f"(c[0]), "+f"(c[1]), "+f"(c[2]), "+f"(c[3])
        : "r"(a[0]), "r"(a[1]), "r"(a[2]), "r"(a[3]), "r"(b[0]), "r"(b[1]));
}
#define CP16(dst, src) \
    asm volatile("cp.async.cg.shared.global [%0], [%1], 16;" :: "r"(dst), "l"(src) : "memory")
#define CP_COMMIT()  asm volatile("cp.async.commit_group;" ::: "memory")
#define CP_WAIT(n)   asm volatile("cp.async.wait_group " #n ";" ::: "memory")

// ---------------------------------------------------------------------------
// Split kernels: produce hi/lo tf32 operands, tiled 128x32 and SW-swizzled
// exactly like the GEMM smem layout, so the GEMM copies are linear cp.async.
// Tile (xb, kt) occupies a contiguous 4096-u32 block at (xb*(K/32)+kt)*4096.
// ---------------------------------------------------------------------------
__global__ __launch_bounds__(256)
void splitA_kernel(const float* __restrict__ A, float* __restrict__ Ah,
                   float* __restrict__ Al, int M, int K)
{
    const int total = (M * K) >> 2;
    int idx = blockIdx.x * blockDim.x + threadIdx.x;
    if (idx >= total) return;
    const int kg = K >> 2;
    const int m  = idx / kg, k4 = idx - m * kg;
    float4 v = *(const float4*)(A + (size_t)m * K + 4 * k4);
    const int mb = m >> 7, row = m & 127, kt = k4 >> 3, c4 = k4 & 7;
    const size_t off = ((size_t)(mb * (K >> 5) + kt)) * 4096
                     + row * 32 + 4 * (c4 ^ (row & 7));
    uint4 hi, lo;
    split_f(v.x, hi.x, lo.x); split_f(v.y, hi.y, lo.y);
    split_f(v.z, hi.z, lo.z); split_f(v.w, hi.w, lo.w);
    *(uint4*)(Ah + off) = hi;
    *(uint4*)(Al + off) = lo;
}

// B [K x N] -> transposed n-major tiles (n rows of 32 k-floats, swizzled)
__global__ __launch_bounds__(256)
void splitB_kernel(const float* __restrict__ B, float* __restrict__ Bh,
                   float* __restrict__ Bl, int K, int N)
{
    const int total = (K * N) >> 2;
    int idx = blockIdx.x * blockDim.x + threadIdx.x;
    if (idx >= total) return;
    const int tile = idx >> 10;           // 1024 granules per tile
    const int g    = idx & 1023;
    const int n    = g & 127, k4 = g >> 7;
    const int nkt  = K >> 5;
    const int nb   = tile / nkt, kt = tile - nb * nkt;
    const int kbase = kt * 32 + 4 * k4;
    const int ncol  = nb * 128 + n;
    uint4 hi, lo;
    split_f(B[(size_t)(kbase + 0) * N + ncol], hi.x, lo.x);
    split_f(B[(size_t)(kbase + 1) * N + ncol], hi.y, lo.y);
    split_f(B[(size_t)(kbase + 2) * N + ncol], hi.z, lo.z);
    split_f(B[(size_t)(kbase + 3) * N + ncol], hi.w, lo.w);
    const size_t off = (size_t)tile * 4096 + n * 32 + 4 * (k4 ^ (n & 7));
    *(uint4*)(Bh + off) = hi;
    *(uint4*)(Bl + off) = lo;
}

// ---------------------------------------------------------------------------
// 3xTF32 GEMM over pre-split operands: C = A*B + bias.
// CTA 128x128x32, 256 thr = 8 warps (4m x 2n), warp 32x64.  3-stage cp.async
// ring (64KB/stage); mainloop identical to the proven R5 compute block.
// Stage layout (bytes): Ah[16384] | Al[16384] | Bh[16384] | Bl[16384].
// ---------------------------------------------------------------------------
#define GST_U32 16384
#define G_SMEM_BYTES (3 * GST_U32 * 4)      // 196608

__device__ __forceinline__ void g_issue_stage(
    const float* Ah, const float* Al, const float* Bh, const float* Bl,
    size_t aBase, size_t bBase, int t, uint32_t stage, int tid)
{
    const size_t aOff = aBase + (size_t)t * 4096;
    const size_t bOff = bBase + (size_t)t * 4096;
#pragma unroll
    for (int it = 0; it < 4; ++it) {
        const int g = tid + 256 * it;          // granule id, 16B each
        CP16(stage + g * 16,             Ah + aOff + g * 4);
        CP16(stage + 16384 + g * 16,     Al + aOff + g * 4);
        CP16(stage + 32768 + g * 16,     Bh + bOff + g * 4);
        CP16(stage + 49152 + g * 16,     Bl + bOff + g * 4);
    }
}

__global__ __launch_bounds__(256)
void gemm_ps_kernel(const float* __restrict__ Ah, const float* __restrict__ Al,
                    const float* __restrict__ Bh, const float* __restrict__ Bl,
                    const float* __restrict__ bias, float* __restrict__ C,
                    int M, int N, int K)
{
    extern __shared__ __align__(1024) uint32_t dynsm[];
    const int tid  = threadIdx.x;
    const int lane = tid & 31;
    const int warp = tid >> 5;
    const int wm   = (warp >> 1) * 32;
    const int wn   = (warp & 1) * 64;
    const int m0   = blockIdx.y * 128;
    const int n0   = blockIdx.x * 128;

    const int q = lane >> 3;
    const int r = lane & 7;
    const int rowA0 = wm + 8 * (q & 1) + r;
    const int rowB0 = wn + 8 * (q >> 1) + r;

    const uint32_t smBase = smem_u32(dynsm);
    const int nkt = K >> 5;
    const size_t aBase = (size_t)blockIdx.y * nkt * 4096;
    const size_t bBase = (size_t)blockIdx.x * nkt * 4096;

    float acc[2][8][4];
#pragma unroll
    for (int i = 0; i < 2; i++)
#pragma unroll
        for (int j = 0; j < 8; j++)
#pragma unroll
            for (int v = 0; v < 4; v++) acc[i][j][v] = 0.0f;

    // prologue: tiles 0 and 1
#pragma unroll
    for (int t = 0; t < 2; ++t) {
        g_issue_stage(Ah, Al, Bh, Bl, aBase, bBase, t,
                      smBase + (uint32_t)(t * GST_U32 * 4), tid);
        CP_COMMIT();
    }

    for (int t = 0; t < nkt; ++t) {
        CP_WAIT(1);
        __syncthreads();

        if (t + 2 < nkt)
            g_issue_stage(Ah, Al, Bh, Bl, aBase, bBase, t + 2,
                          smBase + (uint32_t)(((t + 2) % 3) * GST_U32 * 4), tid);
        CP_COMMIT();

        const uint32_t sAh = smBase + (uint32_t)((t % 3) * GST_U32 * 4);
        const uint32_t sAl = sAh + 16384;
        const uint32_t sBh = sAh + 32768;
        const uint32_t sBl = sAh + 49152;

#pragma unroll
        for (int s = 0; s < 4; ++s) {
            const int ka = (2 * s + (q >> 1)) ^ r;
            uint32_t ah[2][4], al[2][4];
#pragma unroll
            for (int mi = 0; mi < 2; ++mi) {
                const uint32_t off = (uint32_t)(((rowA0 + 16 * mi) * 32 + 4 * ka) << 2);
                ldmatrix_x4(ah[mi], sAh + off);
                ldmatrix_x4(al[mi], sAl + off);
            }
            const int kb = (2 * s + (q & 1)) ^ r;
#pragma unroll
            for (int jp = 0; jp < 4; ++jp) {
                const uint32_t off = (uint32_t)(((rowB0 + 16 * jp) * 32 + 4 * kb) << 2);
                uint32_t th[4], tl[4];
                ldmatrix_x4(th, sBh + off);
                ldmatrix_x4(tl, sBl + off);
                uint32_t bh0[2] = { th[0], th[1] }, bh1[2] = { th[2], th[3] };
                uint32_t bl0[2] = { tl[0], tl[1] }, bl1[2] = { tl[2], tl[3] };
#pragma unroll
                for (int mi = 0; mi < 2; ++mi) {
                    mma_tf32(acc[mi][2 * jp], ah[mi], bh0);
                    mma_tf32(acc[mi][2 * jp], ah[mi], bl0);
                    mma_tf32(acc[mi][2 * jp], al[mi], bh0);
                    mma_tf32(acc[mi][2 * jp + 1], ah[mi], bh1);
                    mma_tf32(acc[mi][2 * jp + 1], ah[mi], bl1);
                    mma_tf32(acc[mi][2 * jp + 1], al[mi], bh1);
                }
            }
        }
    }

    // epilogue: acc + bias -> C
    const int gg  = lane >> 2;
    const int tig = lane & 3;
#pragma unroll
    for (int mi = 0; mi < 2; ++mi) {
#pragma unroll
        for (int nj = 0; nj < 8; ++nj) {
            const int row = m0 + wm + 16 * mi + gg;
            const int col = n0 + wn + 8 * nj + 2 * tig;
            const float b0v = __ldg(bias + col);
            const float b1v = __ldg(bias + col + 1);
            float2 v0 = make_float2(acc[mi][nj][0] + b0v, acc[mi][nj][1] + b1v);
            float2 v1 = make_float2(acc[mi][nj][2] + b0v, acc[mi][nj][3] + b1v);
            *(float2*)(C + (size_t)row * N + col)       = v0;
            *(float2*)(C + (size_t)(row + 8) * N + col) = v1;
        }
    }
}

// ---------------------------------------------------------------------------
// RoPE (full rotation, ROT == HD == 128), in-place on Q and K heads.
// ---------------------------------------------------------------------------
__global__ __launch_bounds__(256)
void rope_kernel(float* __restrict__ qkv,
                 const float* __restrict__ cosp,
                 const float* __restrict__ sinp)
{
    const int total = MTOK * (NHH + NKV) * 64;
    int idx = blockIdx.x * blockDim.x + threadIdx.x;
    if (idx >= total) return;
    const int t    = idx / ((NHH + NKV) * 64);
    const int rem  = idx - t * ((NHH + NKV) * 64);
    const int head = rem >> 6;
    const int j    = rem & 63;
    const int base = (head < NHH) ? head * HD : KOFF + (head - NHH) * HD;

    float* p = qkv + (size_t)t * NQKV + base;
    const float x1 = p[j];
    const float x2 = p[j + 64];
    const float* cp = cosp + (size_t)t * 128;
    const float* sp = sinp + (size_t)t * 128;
    p[j]      = x1 * cp[j]      - x2 * sp[j];
    p[j + 64] = x2 * cp[j + 64] + x1 * sp[j + 64];
}

// ---------------------------------------------------------------------------
// Tensor-core flash attention (tf32, mma.sync) — R5 version (proven fastest).
// CTA: 128 q-rows x one head. 8 warps x 16 q-rows. KV tiles of 64.
// ---------------------------------------------------------------------------
#define AT_VS   (64 * 128)
#define AT_PS   (AT_VS + 64 * 136)
#define AT_U32  (AT_PS + 128 * 64)
#define AT_BYTES (AT_U32 * 4)

__global__ __launch_bounds__(256)
void attn_tc_kernel(const float* __restrict__ qkv, float* __restrict__ attn_out)
{
    extern __shared__ __align__(1024) uint32_t dynsm[];
    uint32_t* Ks  = dynsm;
    uint32_t* Vs  = dynsm + AT_VS;
    uint32_t* Ps  = dynsm + AT_PS;
    uint32_t* Qst = dynsm;

    const int tid  = threadIdx.x;
    const int lane = tid & 31;
    const int warp = tid >> 5;
    const int h    = blockIdx.y;
    const int b    = blockIdx.z;
    const int g    = h >> 2;
    const int tq0  = b * SS + blockIdx.x * 128;
    const int wq0  = warp * 16;
    const int qq   = lane >> 3;
    const int r    = lane & 7;
    const int gg   = lane >> 2;
    const int t4   = lane & 3;
    const float scale = 0.08838834764831845f;

    const uint32_t sQ = smem_u32(Qst);
    const uint32_t sK = smem_u32(Ks);
    const uint32_t sP = smem_u32(Ps);

#pragma unroll
    for (int i = 0; i < 16; i++) {
        const int idx = tid + 256 * i;
        const int row = idx >> 5, c4 = idx & 31;
        float4 v = *(const float4*)(qkv + (size_t)(tq0 + row) * NQKV + h * HD + 4 * c4);
        v.x *= scale; v.y *= scale; v.z *= scale; v.w *= scale;
        *(uint4*)&Qst[row * 128 + 4 * (c4 ^ (row & 7))] = tf32x4(v);
    }
    __syncthreads();

    uint32_t qf[16][4];
    {
        const int rowA = wq0 + 8 * (qq & 1) + r;
#pragma unroll
        for (int s = 0; s < 16; s++) {
            const int k4 = (2 * s + (qq >> 1)) ^ r;
            ldmatrix_x4(qf[s], sQ + (uint32_t)((rowA * 128 + 4 * k4) << 2));
        }
    }
    __syncthreads();

    float O[16][4];
#pragma unroll
    for (int i = 0; i < 16; i++)
#pragma unroll
        for (int j = 0; j < 4; j++) O[i][j] = 0.0f;
    float m0 = -INFINITY, m1 = -INFINITY, l0 = 0.0f, l1 = 0.0f;

    const int rowB = 8 * (qq >> 1) + r;
    const int rowP = wq0 + 8 * (qq & 1) + r;

    for (int kt = 0; kt < SS / 64; ++kt) {
        const int tk0 = b * SS + kt * 64;
#pragma unroll
        for (int i = 0; i < 8; i++) {
            const int idx = tid + 256 * i;
            const int row = idx >> 5, c4 = idx & 31;
            const float* srck = qkv + (size_t)(tk0 + row) * NQKV + KOFF + g * HD + 4 * c4;
            const float* srcv = qkv + (size_t)(tk0 + row) * NQKV + VOFF + g * HD + 4 * c4;
            *(uint4*)&Ks[row * 128 + 4 * (c4 ^ (row & 7))] = tf32x4(*(const float4*)srck);
            *(uint4*)&Vs[row * 136 + 4 * c4]               = tf32x4(*(const float4*)srcv);
        }
        __syncthreads();

        float sacc[8][4];
#pragma unroll
        for (int nj = 0; nj < 8; nj++)
#pragma unroll
            for (int v = 0; v < 4; v++) sacc[nj][v] = 0.0f;

#pragma unroll
        for (int s = 0; s < 16; s++) {
            uint32_t bf[8][2];
            const int k4 = (2 * s + (qq & 1)) ^ r;
#pragma unroll
            for (int jp = 0; jp < 4; jp++) {
                uint32_t tmp[4];
                ldmatrix_x4(tmp, sK + (uint32_t)(((rowB + 16 * jp) * 128 + 4 * k4) << 2));
                bf[2 * jp][0] = tmp[0]; bf[2 * jp][1] = tmp[1];
                bf[2 * jp + 1][0] = tmp[2]; bf[2 * jp + 1][1] = tmp[3];
            }
#pragma unroll
            for (int nj = 0; nj < 8; nj++)
                mma_tf32(sacc[nj], qf[s], bf[nj]);
        }

        float rm0 = -INFINITY, rm1 = -INFINITY;
#pragma unroll
        for (int nj = 0; nj < 8; nj++) {
            rm0 = fmaxf(rm0, fmaxf(sacc[nj][0], sacc[nj][1]));
            rm1 = fmaxf(rm1, fmaxf(sacc[nj][2], sacc[nj][3]));
        }
        rm0 = fmaxf(rm0, __shfl_xor_sync(0xffffffffu, rm0, 1));
        rm0 = fmaxf(rm0, __shfl_xor_sync(0xffffffffu, rm0, 2));
        rm1 = fmaxf(rm1, __shfl_xor_sync(0xffffffffu, rm1, 1));
        rm1 = fmaxf(rm1, __shfl_xor_sync(0xffffffffu, rm1, 2));

        const float mn0 = fmaxf(m0, rm0), mn1 = fmaxf(m1, rm1);
        const float a0 = __expf(m0 - mn0), a1 = __expf(m1 - mn1);
        float rs0 = 0.0f, rs1 = 0.0f;

        const int prow0 = wq0 + gg;
#pragma unroll
        for (int nj = 0; nj < 8; nj++) {
            const float p0 = __expf(sacc[nj][0] - mn0);
            const float p1 = __expf(sacc[nj][1] - mn0);
            const float p2 = __expf(sacc[nj][2] - mn1);
            const float p3 = __expf(sacc[nj][3] - mn1);
            rs0 += p0 + p1; rs1 += p2 + p3;
            const int c4s = (2 * nj + (t4 >> 1)) ^ gg;
            const int sub = 2 * (t4 & 1);
            *(uint2*)&Ps[prow0 * 64 + 4 * c4s + sub]       = make_uint2(f2tf32(p0), f2tf32(p1));
            *(uint2*)&Ps[(prow0 + 8) * 64 + 4 * c4s + sub] = make_uint2(f2tf32(p2), f2tf32(p3));
        }
        rs0 += __shfl_xor_sync(0xffffffffu, rs0, 1);
        rs0 += __shfl_xor_sync(0xffffffffu, rs0, 2);
        rs1 += __shfl_xor_sync(0xffffffffu, rs1, 1);
        rs1 += __shfl_xor_sync(0xffffffffu, rs1, 2);
        l0 = l0 * a0 + rs0; m0 = mn0;
        l1 = l1 * a1 + rs1; m1 = mn1;
#pragma unroll
        for (int nt = 0; nt < 16; nt++) {
            O[nt][0] *= a0; O[nt][1] *= a0;
            O[nt][2] *= a1; O[nt][3] *= a1;
        }
        __syncwarp();

#pragma unroll
        for (int s2 = 0; s2 < 8; s2++) {
            uint32_t pf[4];
            const int k4 = (2 * s2 + (qq >> 1)) ^ r;
            ldmatrix_x4(pf, sP + (uint32_t)((rowP * 64 + 4 * k4) << 2));
            const uint32_t* v0 = &Vs[(8 * s2 + t4) * 136 + gg];
            const uint32_t* v1 = &Vs[(8 * s2 + t4 + 4) * 136 + gg];
#pragma unroll
            for (int nd = 0; nd < 16; nd++) {
                uint32_t bb[2] = { v0[8 * nd], v1[8 * nd] };
                mma_tf32(O[nd], pf, bb);
            }
        }
        __syncthreads();
    }

    const float inv0 = 1.0f / l0, inv1 = 1.0f / l1;
    const int row0 = tq0 + wq0 + gg;
    float* d0 = attn_out + (size_t)row0 * HH + h * HD;
    float* d1 = attn_out + (size_t)(row0 + 8) * HH + h * HD;
#pragma unroll
    for (int nd = 0; nd < 16; nd++) {
        const int col = 8 * nd + 2 * t4;
        *(float2*)(d0 + col) = make_float2(O[nd][0] * inv0, O[nd][1] * inv0);
        *(float2*)(d1 + col) = make_float2(O[nd][2] * inv1, O[nd][3] * inv1);
    }
}

// ---------------------------------------------------------------------------
// Launch
// ---------------------------------------------------------------------------
extern "C" void kernel_launch(void* const* d_in, const int* in_sizes, int n_in,
                              void* d_out, int out_size)
{
    (void)in_sizes; (void)n_in; (void)out_size;
    const float* hs    = (const float*)d_in[0];
    const float* cosp  = (const float*)d_in[1];
    const float* sinp  = (const float*)d_in[2];
    const float* w_qkv = (const float*)d_in[3];
    const float* b_qkv = (const float*)d_in[4];
    const float* w_o   = (const float*)d_in[5];
    const float* b_o   = (const float*)d_in[6];
    float* out = (float*)d_out;

    float *qkv, *attn, *Ah, *Al, *Bh, *Bl;
    cudaGetSymbolAddress((void**)&qkv,  g_qkv);
    cudaGetSymbolAddress((void**)&attn, g_attn);
    cudaGetSymbolAddress((void**)&Ah,   g_Ah);
    cudaGetSymbolAddress((void**)&Al,   g_Al);
    cudaGetSymbolAddress((void**)&Bh,   g_Bh);
    cudaGetSymbolAddress((void**)&Bl,   g_Bl);

    cudaFuncSetAttribute((const void*)gemm_ps_kernel,
                         cudaFuncAttributeMaxDynamicSharedMemorySize,
                         G_SMEM_BYTES);
    cudaFuncSetAttribute((const void*)attn_tc_kernel,
                         cudaFuncAttributeMaxDynamicSharedMemorySize,
                         AT_BYTES);

    // 1) Pre-split + relayout operands for QKV GEMM, then GEMM
    splitA_kernel<<<(MTOK * HH / 4 + 255) / 256, 256>>>(hs, Ah, Al, MTOK, HH);
    splitB_kernel<<<(HH * NQKV / 4 + 255) / 256, 256>>>(w_qkv, Bh, Bl, HH, NQKV);
    gemm_ps_kernel<<<dim3(NQKV / 128, MTOK / 128), 256, G_SMEM_BYTES>>>(
        Ah, Al, Bh, Bl, b_qkv, qkv, MTOK, NQKV, HH);

    // 2) RoPE on q and k heads (in-place)
    {
        const int total = MTOK * (NHH + NKV) * 64;
        rope_kernel<<<(total + 255) / 256, 256>>>(qkv, cosp, sinp);
    }

    // 3) Tensor-core flash attention (tf32 mma.sync)
    attn_tc_kernel<<<dim3(SS / 128, NHH, BB), 256, AT_BYTES>>>(qkv, attn);

    // 4) Pre-split + relayout for O-projection, then GEMM -> d_out
    splitA_kernel<<<(MTOK * HH / 4 + 255) / 256, 256>>>(attn, Ah, Al, MTOK, HH);
    splitB_kernel<<<(HH * HH / 4 + 255) / 256, 256>>>(w_o, Bh, Bl, HH, HH);
    gemm_ps_kernel<<<dim3(HH / 128, MTOK / 128), 256, G_SMEM_BYTES>>>(
        Ah, Al, Bh, Bl, b_o, out, MTOK, HH, HH);
}